// round 4
// baseline (speedup 1.0000x reference)
#include <cuda_runtime.h>
#include <float.h>
#include <stdint.h>

#define NJOINT 17
#define HH 512
#define WW 512
#define HW (HH * WW)
#define TOPK 30
#define MAXPEAKS 16384

// ---------------- scratch (device globals: no allocations allowed) ----------
__device__ int    g_count[NJOINT];
__device__ float  g_pval[NJOINT][MAXPEAKS];
__device__ int    g_pidx[NJOINT][MAXPEAKS];
__device__ float2 g_hxy[NJOINT][TOPK];

// ---------------- kernel 0: zero peak counters (graph replay safe) ----------
__global__ void zero_kernel() {
    if (threadIdx.x < NJOINT) g_count[threadIdx.x] = 0;
}

// ---------------- kernel 1: 5x5 NMS + peak compaction ----------------------
// Tile 128x8 per block, halo 2, separable max in shared memory.
__global__ void __launch_bounds__(1024) nms_kernel(const float* __restrict__ heat) {
    __shared__ float s[12][132];    // rows 8+4, cols 128+4
    __shared__ float rm[12][128];   // row-max per (row, out-col)
    __shared__ float stv[1024];
    __shared__ int   sti[1024];
    __shared__ int   scnt;
    __shared__ int   sbase;

    const int tid = threadIdx.x;
    const int j   = blockIdx.z;
    const int gx0 = blockIdx.x * 128 - 2;
    const int gy0 = blockIdx.y * 8   - 2;
    const float* hj = heat + (size_t)j * HW;

    if (tid == 0) scnt = 0;

    // load tile with halo; out-of-bounds = -FLT_MAX (heat >= 0, acts as -inf pad)
    for (int i = tid; i < 12 * 132; i += 1024) {
        int ly = i / 132, lx = i - ly * 132;
        int gx = gx0 + lx, gy = gy0 + ly;
        float v = -FLT_MAX;
        if (gx >= 0 && gx < WW && gy >= 0 && gy < HH)
            v = __ldg(hj + gy * WW + gx);
        s[ly][lx] = v;
    }
    __syncthreads();

    // horizontal 5-max
    for (int i = tid; i < 12 * 128; i += 1024) {
        int ly = i >> 7, lx = i & 127;
        float m = s[ly][lx];
        m = fmaxf(m, s[ly][lx + 1]);
        m = fmaxf(m, s[ly][lx + 2]);
        m = fmaxf(m, s[ly][lx + 3]);
        m = fmaxf(m, s[ly][lx + 4]);
        rm[ly][lx] = m;
    }
    __syncthreads();

    // vertical 5-max + peak test (center included in window: peak iff c == m)
    {
        int tx = tid & 127, ty = tid >> 7;
        float c = s[ty + 2][tx + 2];
        float m = rm[ty][tx];
        m = fmaxf(m, rm[ty + 1][tx]);
        m = fmaxf(m, rm[ty + 2][tx]);
        m = fmaxf(m, rm[ty + 3][tx]);
        m = fmaxf(m, rm[ty + 4][tx]);
        if (c == m) {
            int p = atomicAdd(&scnt, 1);
            stv[p] = c;
            sti[p] = (gy0 + ty + 2) * WW + (gx0 + tx + 2);
        }
    }
    __syncthreads();

    if (tid == 0) sbase = atomicAdd(&g_count[j], scnt);
    __syncthreads();

    const int cnt = scnt, base = sbase;
    for (int i = tid; i < cnt; i += 1024) {
        int d = base + i;
        if (d < MAXPEAKS) {
            g_pval[j][d] = stv[i];
            g_pidx[j][d] = sti[i];
        }
    }
}

// ---------------- kernel 2: top-30 per joint + heat_xy ---------------------
__device__ __forceinline__ bool better(float v1, int i1, float v2, int i2) {
    // descending value, ascending index tie-break (jax.lax.top_k stable order)
    return (v1 > v2) || (v1 == v2 && i1 < i2);
}

__global__ void __launch_bounds__(1024) topk_kernel(const float* __restrict__ off,
                                                    const int* __restrict__ stride_p) {
    __shared__ float sv[32];
    __shared__ int   si[32];
    __shared__ float winv[TOPK];
    __shared__ int   wini[TOPK];

    const int tid = threadIdx.x;
    const int j   = blockIdx.x;
    int n = g_count[j];
    if (n > MAXPEAKS) n = MAXPEAKS;

    // register-resident strided slice of the peak list
    float v[16];
    int   id[16];
#pragma unroll
    for (int s2 = 0; s2 < 16; s2++) {
        int i = tid + s2 * 1024;
        if (i < n) { v[s2] = g_pval[j][i]; id[s2] = g_pidx[j][i]; }
        else       { v[s2] = -FLT_MAX;     id[s2] = 0x7fffffff;   }
    }

    for (int r = 0; r < TOPK; r++) {
        float bv = -FLT_MAX;
        int   bi = 0x7fffffff;
#pragma unroll
        for (int s2 = 0; s2 < 16; s2++)
            if (better(v[s2], id[s2], bv, bi)) { bv = v[s2]; bi = id[s2]; }

#pragma unroll
        for (int o = 16; o > 0; o >>= 1) {
            float ov = __shfl_down_sync(0xffffffffu, bv, o);
            int   oi = __shfl_down_sync(0xffffffffu, bi, o);
            if (better(ov, oi, bv, bi)) { bv = ov; bi = oi; }
        }
        if ((tid & 31) == 0) { sv[tid >> 5] = bv; si[tid >> 5] = bi; }
        __syncthreads();
        if (tid < 32) {
            bv = sv[tid]; bi = si[tid];
#pragma unroll
            for (int o = 16; o > 0; o >>= 1) {
                float ov = __shfl_down_sync(0xffffffffu, bv, o);
                int   oi = __shfl_down_sync(0xffffffffu, bi, o);
                if (better(ov, oi, bv, bi)) { bv = ov; bi = oi; }
            }
            if (tid == 0) { winv[r] = bv; wini[r] = bi; }
        }
        __syncthreads();
        const int w = wini[r];
#pragma unroll
        for (int s2 = 0; s2 < 16; s2++)
            if (id[s2] == w) v[s2] = -FLT_MAX;  // remove winner (indices unique)
    }

    if (tid < TOPK) {
        int idx = wini[tid];
        if (idx < 0 || idx >= HW) idx = 0;  // degenerate safety
        float x = (float)(idx & (WW - 1));
        float y = (float)(idx >> 9);
        float ox = __ldg(off + (size_t)(j * 2 + 0) * HW + idx);
        float oy = __ldg(off + (size_t)(j * 2 + 1) * HW + idx);
        float st = (float)(*stride_p);
        float2 r2;
        r2.x = __fmul_rn(st, __fadd_rn(x, ox));   // bit-exact vs reference
        r2.y = __fmul_rn(st, __fadd_rn(y, oy));
        g_hxy[j][tid] = r2;
    }
}

// ---------------- kernel 3: nearest-candidate assignment -------------------
__global__ void __launch_bounds__(256) assign_kernel(const float2* __restrict__ poses,
                                                     float2* __restrict__ out,
                                                     int total) {
    __shared__ float2 sh[NJOINT * TOPK];
    const int tid = threadIdx.x;
    const float2* hx = &g_hxy[0][0];
    for (int i = tid; i < NJOINT * TOPK; i += 256) sh[i] = hx[i];
    __syncthreads();

    int t = blockIdx.x * 256 + tid;
    if (t >= total) return;

    const int j = t % NJOINT;
    const float2 p = poses[t];
    const float2* cand = sh + j * TOPK;

    float d2a[TOPK];
    float bd = FLT_MAX;
    int best = 0;
#pragma unroll
    for (int k = 0; k < TOPK; k++) {
        float2 c  = cand[k];
        float dx  = __fadd_rn(p.x, -c.x);
        float dy  = __fadd_rn(p.y, -c.y);
        float d   = __fadd_rn(__fmul_rn(dx, dx), __fmul_rn(dy, dy));
        d2a[k] = d;
        if (d < bd) { bd = d; best = k; }   // strict <: keeps first occurrence
    }

    // Reference argmins over rounded sqrt(d2). sqrt can collapse two strictly
    // ordered d2 into equal floats, making the EARLIER index win. Only possible
    // when d2a[k] is within ~2.4e-7 relative of bd — gate the sqrt path on that.
    bool anyclose = false;
    const float thr = __fmul_rn(bd, 1e-6f);
#pragma unroll
    for (int k = 0; k < TOPK; k++)
        anyclose |= (k < best) && (__fadd_rn(d2a[k], -bd) <= thr);

    if (anyclose) {
        float rb = sqrtf(bd);  // min of rounded sqrts == sqrt of min d2 (monotone)
        for (int k = 0; k < best; k++) {
            float2 c = cand[k];
            float dx = __fadd_rn(p.x, -c.x);
            float dy = __fadd_rn(p.y, -c.y);
            float d  = __fadd_rn(__fmul_rn(dx, dx), __fmul_rn(dy, dy));
            if (__fadd_rn(d, -bd) <= thr && sqrtf(d) == rb) { best = k; break; }
        }
    }

    out[t] = cand[best];
}

// ---------------- launch ----------------------------------------------------
extern "C" void kernel_launch(void* const* d_in, const int* in_sizes, int n_in,
                              void* d_out, int out_size) {
    const float* poses    = (const float*)d_in[0];   // (N, 2*17) f32
    const float* heat     = (const float*)d_in[1];   // (17, 512, 512) f32
    const float* off      = (const float*)d_in[2];   // (17, 2, 512, 512) f32
    const int*   stride_p = (const int*)d_in[3];     // scalar

    const int total = in_sizes[0] / 2;               // N * 17 float2 pairs

    zero_kernel<<<1, 32>>>();

    dim3 g_nms(WW / 128, HH / 8, NJOINT);            // (4, 64, 17)
    nms_kernel<<<g_nms, 1024>>>(heat);

    topk_kernel<<<NJOINT, 1024>>>(off, stride_p);

    assign_kernel<<<(total + 255) / 256, 256>>>((const float2*)poses,
                                                (float2*)d_out, total);
}

// round 5
// speedup vs baseline: 1.0661x; 1.0661x over previous
#include <cuda_runtime.h>
#include <float.h>
#include <stdint.h>

#define NJOINT 17
#define HH 512
#define WW 512
#define HW (HH * WW)
#define TOPK 30
#define MAXPEAKS 16384

// ---------------- scratch (device globals: no allocations allowed) ----------
__device__ int    g_count[NJOINT];
__device__ float  g_pval[NJOINT][MAXPEAKS];
__device__ int    g_pidx[NJOINT][MAXPEAKS];
__device__ float2 g_hxy[NJOINT][TOPK];

// ---------------- packed f32x2 helpers (Blackwell fp32x2 pipe) --------------
__device__ __forceinline__ unsigned long long pk2(float lo, float hi) {
    unsigned long long r;
    asm("mov.b64 %0, {%1, %2};" : "=l"(r) : "f"(lo), "f"(hi));
    return r;
}
__device__ __forceinline__ void upk2(float& lo, float& hi, unsigned long long v) {
    asm("mov.b64 {%0, %1}, %2;" : "=f"(lo), "=f"(hi) : "l"(v));
}
__device__ __forceinline__ unsigned long long add2(unsigned long long a, unsigned long long b) {
    unsigned long long r;
    asm("add.rn.f32x2 %0, %1, %2;" : "=l"(r) : "l"(a), "l"(b));
    return r;
}
__device__ __forceinline__ unsigned long long mul2(unsigned long long a, unsigned long long b) {
    unsigned long long r;
    asm("mul.rn.f32x2 %0, %1, %2;" : "=l"(r) : "l"(a), "l"(b));
    return r;
}
__device__ __forceinline__ unsigned long long fma2(unsigned long long a, unsigned long long b,
                                                   unsigned long long c) {
    unsigned long long r;
    asm("fma.rn.f32x2 %0, %1, %2, %3;" : "=l"(r) : "l"(a), "l"(b), "l"(c));
    return r;
}

// ---------------- kernel 0: zero peak counters (graph replay safe) ----------
__global__ void zero_kernel() {
    if (threadIdx.x < NJOINT) g_count[threadIdx.x] = 0;
}

// ---------------- kernel 1: 5x5 NMS + peak compaction ----------------------
// Tile 128x32 per block (4 outputs/thread), halo 2, separable max.
#define TW 128
#define TH 32
#define LR (TH + 4)   // 36 loaded rows
#define LC (TW + 4)   // 132 loaded cols
#define STAGE 512

__global__ void __launch_bounds__(1024) nms_kernel(const float* __restrict__ heat) {
    __shared__ float s[LR][LC];     // 19.0 KB
    __shared__ float rm[LR][TW];    // 18.4 KB row-max
    __shared__ float stv[STAGE];
    __shared__ int   sti[STAGE];
    __shared__ int   scnt;
    __shared__ int   sbase;

    const int tid = threadIdx.x;
    const int j   = blockIdx.z;
    const int gx0 = blockIdx.x * TW - 2;
    const int gy0 = blockIdx.y * TH - 2;
    const float* hj = heat + (size_t)j * HW;

    if (tid == 0) scnt = 0;

    // load tile with halo; OOB = -FLT_MAX (heat >= 0, acts as -inf pad)
    for (int i = tid; i < LR * LC; i += 1024) {
        int ly = i / LC, lx = i - ly * LC;
        int gx = gx0 + lx, gy = gy0 + ly;
        float v = -FLT_MAX;
        if ((unsigned)gx < WW && (unsigned)gy < HH)
            v = __ldg(hj + gy * WW + gx);
        s[ly][lx] = v;
    }
    __syncthreads();

    // horizontal 5-max
    for (int i = tid; i < LR * TW; i += 1024) {
        int ly = i >> 7, lx = i & 127;
        float m = fmaxf(fmaxf(fmaxf(s[ly][lx], s[ly][lx + 1]),
                              fmaxf(s[ly][lx + 2], s[ly][lx + 3])),
                        s[ly][lx + 4]);
        rm[ly][lx] = m;
    }
    __syncthreads();

    // vertical 5-max over 4 consecutive output rows per thread (shared partials)
    {
        const int tx  = tid & 127;
        const int ty0 = (tid >> 7) * 4;
        float a0 = rm[ty0 + 0][tx], a1 = rm[ty0 + 1][tx];
        float a2 = rm[ty0 + 2][tx], a3 = rm[ty0 + 3][tx];
        float a4 = rm[ty0 + 4][tx], a5 = rm[ty0 + 5][tx];
        float a6 = rm[ty0 + 6][tx], a7 = rm[ty0 + 7][tx];
        float t12 = fmaxf(a1, a2), t34 = fmaxf(a3, a4), t56 = fmaxf(a5, a6);
        float m0 = fmaxf(a0, fmaxf(t12, t34));
        float m1 = fmaxf(t12, fmaxf(t34, a5));
        float m2 = fmaxf(a2, fmaxf(t34, t56));
        float m3 = fmaxf(t34, fmaxf(t56, a7));

        float c0 = s[ty0 + 2][tx + 2];
        float c1 = s[ty0 + 3][tx + 2];
        float c2 = s[ty0 + 4][tx + 2];
        float c3 = s[ty0 + 5][tx + 2];

        float mm[4] = {m0, m1, m2, m3};
        float cc[4] = {c0, c1, c2, c3};
#pragma unroll
        for (int r = 0; r < 4; r++) {
            if (cc[r] == mm[r]) {
                int p = atomicAdd(&scnt, 1);
                if (p < STAGE) {
                    stv[p] = cc[r];
                    sti[p] = (gy0 + ty0 + r + 2) * WW + (gx0 + tx + 2);
                }
            }
        }
    }
    __syncthreads();

    if (tid == 0) sbase = atomicAdd(&g_count[j], min(scnt, STAGE));
    __syncthreads();

    const int cnt = min(scnt, STAGE), base = sbase;
    for (int i = tid; i < cnt; i += 1024) {
        int d = base + i;
        if (d < MAXPEAKS) {
            g_pval[j][d] = stv[i];
            g_pidx[j][d] = sti[i];
        }
    }
}

// ---------------- kernel 2: top-30 per joint + heat_xy ---------------------
__device__ __forceinline__ bool better(float v1, int i1, float v2, int i2) {
    // descending value, ascending index tie-break (jax.lax.top_k stable order)
    return (v1 > v2) || (v1 == v2 && i1 < i2);
}

template <int NR>
__device__ __forceinline__ void warp_top30(float* v, int* id,
                                           float* outv, int* outi) {
    // warp-collective: all 32 lanes participate; lane 0 writes winners.
    for (int r = 0; r < TOPK; r++) {
        float bv = -FLT_MAX;
        int   bi = 0x7fffffff;
#pragma unroll
        for (int s = 0; s < NR; s++)
            if (better(v[s], id[s], bv, bi)) { bv = v[s]; bi = id[s]; }
#pragma unroll
        for (int o = 16; o > 0; o >>= 1) {
            float ov = __shfl_down_sync(0xffffffffu, bv, o);
            int   oi = __shfl_down_sync(0xffffffffu, bi, o);
            if (better(ov, oi, bv, bi)) { bv = ov; bi = oi; }
        }
        bv = __shfl_sync(0xffffffffu, bv, 0);
        bi = __shfl_sync(0xffffffffu, bi, 0);
        if ((threadIdx.x & 31) == 0) { outv[r] = bv; outi[r] = bi; }
#pragma unroll
        for (int s = 0; s < NR; s++)
            if (id[s] == bi) v[s] = -FLT_MAX;  // winner ids unique
    }
}

__global__ void __launch_bounds__(1024) topk_kernel(const float* __restrict__ off,
                                                    const int* __restrict__ stride_p) {
    __shared__ float wv1[32][TOPK];
    __shared__ int   wi1[32][TOPK];
    __shared__ float wv2[8][TOPK];
    __shared__ int   wi2[8][TOPK];
    __shared__ float fv[TOPK];
    __shared__ int   fi[TOPK];

    const int tid  = threadIdx.x;
    const int w    = tid >> 5;
    const int lane = tid & 31;
    const int j    = blockIdx.x;
    int n = g_count[j];
    if (n > MAXPEAKS) n = MAXPEAKS;

    // stage 1: each warp does a barrier-free top-30 over its 512-slot slice
    {
        float v[16];
        int   id[16];
#pragma unroll
        for (int s = 0; s < 16; s++) {
            int i = tid + s * 1024;
            if (i < n) { v[s] = g_pval[j][i]; id[s] = g_pidx[j][i]; }
            else       { v[s] = -FLT_MAX;     id[s] = 0x7fffffff;   }
        }
        warp_top30<16>(v, id, wv1[w], wi1[w]);
    }
    __syncthreads();

    // stage 2: warps 0..7 each merge 4 lists (120 entries)
    if (w < 8) {
        float v2[4];
        int   id2[4];
#pragma unroll
        for (int s = 0; s < 4; s++) {
            int e = lane + 32 * s;
            if (e < 4 * TOPK) {
                int L = w * 4 + e / TOPK, r = e % TOPK;
                v2[s] = wv1[L][r]; id2[s] = wi1[L][r];
            } else { v2[s] = -FLT_MAX; id2[s] = 0x7fffffff; }
        }
        warp_top30<4>(v2, id2, wv2[w], wi2[w]);
    }
    __syncthreads();

    // stage 3: warp 0 merges 8 lists (240 entries)
    if (w == 0) {
        float v3[8];
        int   id3[8];
#pragma unroll
        for (int s = 0; s < 8; s++) {
            int e = lane + 32 * s;
            if (e < 8 * TOPK) {
                int L = e / TOPK, r = e % TOPK;
                v3[s] = wv2[L][r]; id3[s] = wi2[L][r];
            } else { v3[s] = -FLT_MAX; id3[s] = 0x7fffffff; }
        }
        warp_top30<8>(v3, id3, fv, fi);
    }
    __syncthreads();

    if (tid < TOPK) {
        int idx = fi[tid];
        if (idx < 0 || idx >= HW) idx = 0;  // degenerate safety
        float x = (float)(idx & (WW - 1));
        float y = (float)(idx >> 9);
        float ox = __ldg(off + (size_t)(j * 2 + 0) * HW + idx);
        float oy = __ldg(off + (size_t)(j * 2 + 1) * HW + idx);
        float st = (float)(*stride_p);
        float2 r2;
        r2.x = __fmul_rn(st, __fadd_rn(x, ox));   // bit-exact vs reference
        r2.y = __fmul_rn(st, __fadd_rn(y, oy));
        g_hxy[j][tid] = r2;
    }
}

// ---------------- kernel 3: nearest-candidate assignment -------------------
// Packed f32x2 distance math (2 candidates / instruction group), conflict-free
// smem layout, exact-rn slow path triggered only when >1 candidate lies within
// 1.2e-6 relative of the min (covers both sqrt-rounding ties AND the fma-vs-rn
// rounding delta, each bounded by ~2.4e-7 relative).
__global__ void __launch_bounds__(256) assign_kernel(const float2* __restrict__ poses,
                                                     float2* __restrict__ out,
                                                     int total) {
    __shared__ float2 sXn[TOPK / 2][NJOINT];  // (-c.x[2p], -c.x[2p+1]) per joint
    __shared__ float2 sYn[TOPK / 2][NJOINT];
    __shared__ float2 sO[NJOINT][TOPK];       // original candidates for output

    const int tid = threadIdx.x;
    for (int i = tid; i < NJOINT * TOPK; i += 256) {
        int jj = i / TOPK, kk = i % TOPK;
        sO[jj][kk] = g_hxy[jj][kk];
    }
    for (int i = tid; i < (TOPK / 2) * NJOINT; i += 256) {
        int p = i / NJOINT, jj = i % NJOINT;
        float2 a = g_hxy[jj][2 * p];
        float2 b = g_hxy[jj][2 * p + 1];
        sXn[p][jj] = make_float2(-a.x, -b.x);
        sYn[p][jj] = make_float2(-a.y, -b.y);
    }
    __syncthreads();

    const int t = blockIdx.x * 256 + tid;
    if (t >= total) return;

    const int j = t % NJOINT;
    const float2 p = poses[t];
    const unsigned long long pxx = pk2(p.x, p.x);
    const unsigned long long pyy = pk2(p.y, p.y);

    float d2a[TOPK];
    float bd = FLT_MAX;
#pragma unroll
    for (int q = 0; q < TOPK / 2; q++) {
        unsigned long long cx = *reinterpret_cast<const unsigned long long*>(&sXn[q][j]);
        unsigned long long cy = *reinterpret_cast<const unsigned long long*>(&sYn[q][j]);
        unsigned long long dx = add2(pxx, cx);
        unsigned long long dy = add2(pyy, cy);
        unsigned long long d2 = fma2(dy, dy, mul2(dx, dx));
        float d0, d1;
        upk2(d0, d1, d2);
        d2a[2 * q]     = d0;
        d2a[2 * q + 1] = d1;
        bd = fminf(bd, fminf(d0, d1));
    }

    // close-set count: how many candidates are within 1.2e-6 relative of min?
    const float bdthr = __fmul_rn(bd, 1.0000012f);
    int nclose = 0;
#pragma unroll
    for (int k = 0; k < TOPK; k++) nclose += (d2a[k] <= bdthr) ? 1 : 0;

    int best = 0;
    if (nclose == 1) {
        // unique min: rn ordering == fma ordering == sqrt ordering here
#pragma unroll
        for (int k = TOPK - 1; k >= 0; k--)
            if (d2a[k] == bd) best = k;
    } else {
        // rare slow path: replicate reference verbatim — exact rn d2, IEEE
        // sqrt, first-occurrence argmin over sqrt values.
        float bs = FLT_MAX;
        for (int k = 0; k < TOPK; k++) {
            float2 c  = sO[j][k];
            float dx  = __fadd_rn(p.x, -c.x);
            float dy  = __fadd_rn(p.y, -c.y);
            float d   = __fadd_rn(__fmul_rn(dx, dx), __fmul_rn(dy, dy));
            float sq  = sqrtf(d);
            if (sq < bs) { bs = sq; best = k; }   // strict <: first occurrence
        }
    }

    out[t] = sO[j][best];
}

// ---------------- launch ----------------------------------------------------
extern "C" void kernel_launch(void* const* d_in, const int* in_sizes, int n_in,
                              void* d_out, int out_size) {
    const float* poses    = (const float*)d_in[0];   // (N, 2*17) f32
    const float* heat     = (const float*)d_in[1];   // (17, 512, 512) f32
    const float* off      = (const float*)d_in[2];   // (17, 2, 512, 512) f32
    const int*   stride_p = (const int*)d_in[3];     // scalar

    const int total = in_sizes[0] / 2;               // N * 17 float2 pairs

    zero_kernel<<<1, 32>>>();

    dim3 g_nms(WW / TW, HH / TH, NJOINT);            // (4, 16, 17)
    nms_kernel<<<g_nms, 1024>>>(heat);

    topk_kernel<<<NJOINT, 1024>>>(off, stride_p);

    assign_kernel<<<(total + 255) / 256, 256>>>((const float2*)poses,
                                                (float2*)d_out, total);
}

// round 8
// speedup vs baseline: 1.3784x; 1.2930x over previous
#include <cuda_runtime.h>
#include <float.h>
#include <stdint.h>

#define NJOINT 17
#define HH 512
#define WW 512
#define HW (HH * WW)
#define TOPK 30
#define MAXPEAKS 16384
#define HICAP 1024
#define HTHR 0.999f

// ---------------- scratch (device globals, zero-init at module load) --------
__device__ int    g_count[NJOINT];
__device__ int    g_cnth[NJOINT];
__device__ float  g_pval[NJOINT][MAXPEAKS];
__device__ int    g_pidx[NJOINT][MAXPEAKS];
__device__ float  g_hval[NJOINT][HICAP];
__device__ int    g_hidx[NJOINT][HICAP];
__device__ float2 g_hxy[NJOINT][TOPK];

// ---------------- packed f32x2 helpers --------------------------------------
__device__ __forceinline__ unsigned long long pk2(float lo, float hi) {
    unsigned long long r;
    asm("mov.b64 %0, {%1, %2};" : "=l"(r) : "f"(lo), "f"(hi));
    return r;
}
__device__ __forceinline__ void upk2(float& lo, float& hi, unsigned long long v) {
    asm("mov.b64 {%0, %1}, %2;" : "=f"(lo), "=f"(hi) : "l"(v));
}
__device__ __forceinline__ unsigned long long add2(unsigned long long a, unsigned long long b) {
    unsigned long long r;
    asm("add.rn.f32x2 %0, %1, %2;" : "=l"(r) : "l"(a), "l"(b));
    return r;
}
__device__ __forceinline__ unsigned long long mul2(unsigned long long a, unsigned long long b) {
    unsigned long long r;
    asm("mul.rn.f32x2 %0, %1, %2;" : "=l"(r) : "l"(a), "l"(b));
    return r;
}
__device__ __forceinline__ unsigned long long fma2(unsigned long long a, unsigned long long b,
                                                   unsigned long long c) {
    unsigned long long r;
    asm("fma.rn.f32x2 %0, %1, %2, %3;" : "=l"(r) : "l"(a), "l"(b), "l"(c));
    return r;
}

// ---------------- kernel 1: 5x5 NMS + peak compaction -----------------------
#define TW 128
#define TH 32
#define LR (TH + 4)
#define LC (TW + 4)
#define STAGE 512

__global__ void __launch_bounds__(1024) nms_kernel(const float* __restrict__ heat) {
    __shared__ float s[LR][LC];
    __shared__ float rm[LR][TW];
    __shared__ float stv[STAGE];
    __shared__ int   sti[STAGE];
    __shared__ int   scnt;
    __shared__ int   sbase;

    const int tid = threadIdx.x;
    const int j   = blockIdx.z;
    const int gx0 = blockIdx.x * TW - 2;
    const int gy0 = blockIdx.y * TH - 2;
    const float* hj = heat + (size_t)j * HW;

    if (tid == 0) scnt = 0;

    const bool interior = (gx0 >= 0) & (gx0 + LC <= WW) & (gy0 >= 0) & (gy0 + LR <= HH);
    if (interior) {
        for (int i = tid; i < LR * LC; i += 1024) {
            int ly = i / LC, lx = i - ly * LC;
            s[ly][lx] = __ldg(hj + (gy0 + ly) * WW + gx0 + lx);
        }
    } else {
        for (int i = tid; i < LR * LC; i += 1024) {
            int ly = i / LC, lx = i - ly * LC;
            int gx = gx0 + lx, gy = gy0 + ly;
            float v = -FLT_MAX;
            if ((unsigned)gx < WW && (unsigned)gy < HH)
                v = __ldg(hj + gy * WW + gx);
            s[ly][lx] = v;
        }
    }
    __syncthreads();

    // horizontal 5-max
    for (int i = tid; i < LR * TW; i += 1024) {
        int ly = i >> 7, lx = i & 127;
        float m = fmaxf(fmaxf(fmaxf(s[ly][lx], s[ly][lx + 1]),
                              fmaxf(s[ly][lx + 2], s[ly][lx + 3])),
                        s[ly][lx + 4]);
        rm[ly][lx] = m;
    }
    __syncthreads();

    // vertical 5-max, 4 output rows per thread (shared partials)
    {
        const int tx  = tid & 127;
        const int ty0 = (tid >> 7) * 4;
        float a0 = rm[ty0 + 0][tx], a1 = rm[ty0 + 1][tx];
        float a2 = rm[ty0 + 2][tx], a3 = rm[ty0 + 3][tx];
        float a4 = rm[ty0 + 4][tx], a5 = rm[ty0 + 5][tx];
        float a6 = rm[ty0 + 6][tx], a7 = rm[ty0 + 7][tx];
        float t12 = fmaxf(a1, a2), t34 = fmaxf(a3, a4), t56 = fmaxf(a5, a6);
        float mm[4];
        mm[0] = fmaxf(a0, fmaxf(t12, t34));
        mm[1] = fmaxf(t12, fmaxf(t34, a5));
        mm[2] = fmaxf(a2, fmaxf(t34, t56));
        mm[3] = fmaxf(t34, fmaxf(t56, a7));
        float cc[4];
        cc[0] = s[ty0 + 2][tx + 2];
        cc[1] = s[ty0 + 3][tx + 2];
        cc[2] = s[ty0 + 4][tx + 2];
        cc[3] = s[ty0 + 5][tx + 2];
#pragma unroll
        for (int r = 0; r < 4; r++) {
            if (cc[r] == mm[r]) {
                int idx = (gy0 + ty0 + r + 2) * WW + (gx0 + tx + 2);
                int p = atomicAdd(&scnt, 1);
                if (p < STAGE) { stv[p] = cc[r]; sti[p] = idx; }
                if (cc[r] > HTHR) {
                    int hp = atomicAdd(&g_cnth[j], 1);
                    if (hp < HICAP) { g_hval[j][hp] = cc[r]; g_hidx[j][hp] = idx; }
                }
            }
        }
    }
    __syncthreads();

    if (tid == 0) sbase = atomicAdd(&g_count[j], min(scnt, STAGE));
    __syncthreads();

    const int cnt = min(scnt, STAGE), base = sbase;
    for (int i = tid; i < cnt; i += 1024) {
        int d = base + i;
        if (d < MAXPEAKS) {
            g_pval[j][d] = stv[i];
            g_pidx[j][d] = sti[i];
        }
    }
}

// ---------------- kernel 2: top-30 per joint + heat_xy ----------------------
__device__ __forceinline__ bool better(float v1, int i1, float v2, int i2) {
    // descending value, ascending index tie-break (jax.lax.top_k stable order)
    return (v1 > v2) || (v1 == v2 && i1 < i2);
}

template <int NR>
__device__ __forceinline__ void warp_top30(float* v, int* id, float* outv, int* outi) {
    for (int r = 0; r < TOPK; r++) {
        float bv = -FLT_MAX;
        int   bi = 0x7fffffff;
#pragma unroll
        for (int s = 0; s < NR; s++)
            if (better(v[s], id[s], bv, bi)) { bv = v[s]; bi = id[s]; }
#pragma unroll
        for (int o = 16; o > 0; o >>= 1) {
            float ov = __shfl_down_sync(0xffffffffu, bv, o);
            int   oi = __shfl_down_sync(0xffffffffu, bi, o);
            if (better(ov, oi, bv, bi)) { bv = ov; bi = oi; }
        }
        bv = __shfl_sync(0xffffffffu, bv, 0);
        bi = __shfl_sync(0xffffffffu, bi, 0);
        if ((threadIdx.x & 31) == 0) { outv[r] = bv; outi[r] = bi; }
#pragma unroll
        for (int s = 0; s < NR; s++)
            if (id[s] == bi) v[s] = -FLT_MAX;  // winner ids unique
    }
}

__global__ void __launch_bounds__(1024) topk_kernel(const float* __restrict__ off,
                                                    const int* __restrict__ stride_p) {
    __shared__ float wv1[32][TOPK];
    __shared__ int   wi1[32][TOPK];
    __shared__ float wv2[8][TOPK];
    __shared__ int   wi2[8][TOPK];
    __shared__ float fv[TOPK];
    __shared__ int   fi[TOPK];

    const int tid  = threadIdx.x;
    const int w    = tid >> 5;
    const int lane = tid & 31;
    const int j    = blockIdx.x;

    const int n_high = g_cnth[j];
    const bool useHigh = (n_high >= TOPK) && (n_high <= HICAP);

    if (useHigh) {
        // fast path: all top-30 values exceed HTHR and live in the high list
        float v[1];
        int   id[1];
        if (tid < n_high) { v[0] = g_hval[j][tid]; id[0] = g_hidx[j][tid]; }
        else              { v[0] = -FLT_MAX;       id[0] = 0x7fffffff;     }
        warp_top30<1>(v, id, wv1[w], wi1[w]);
    } else {
        int n = g_count[j];
        if (n > MAXPEAKS) n = MAXPEAKS;
        float v[16];
        int   id[16];
#pragma unroll
        for (int s = 0; s < 16; s++) {
            int i = tid + s * 1024;
            if (i < n) { v[s] = g_pval[j][i]; id[s] = g_pidx[j][i]; }
            else       { v[s] = -FLT_MAX;     id[s] = 0x7fffffff;   }
        }
        warp_top30<16>(v, id, wv1[w], wi1[w]);
    }
    __syncthreads();

    if (w < 8) {  // merge 4 warp lists each
        float v2[4];
        int   id2[4];
#pragma unroll
        for (int s = 0; s < 4; s++) {
            int e = lane + 32 * s;
            if (e < 4 * TOPK) {
                int L = w * 4 + e / TOPK, r = e % TOPK;
                v2[s] = wv1[L][r]; id2[s] = wi1[L][r];
            } else { v2[s] = -FLT_MAX; id2[s] = 0x7fffffff; }
        }
        warp_top30<4>(v2, id2, wv2[w], wi2[w]);
    }
    __syncthreads();

    if (w == 0) {  // final merge of 8 lists
        float v3[8];
        int   id3[8];
#pragma unroll
        for (int s = 0; s < 8; s++) {
            int e = lane + 32 * s;
            if (e < 8 * TOPK) {
                int L = e / TOPK, r = e % TOPK;
                v3[s] = wv2[L][r]; id3[s] = wi2[L][r];
            } else { v3[s] = -FLT_MAX; id3[s] = 0x7fffffff; }
        }
        warp_top30<8>(v3, id3, fv, fi);
    }
    __syncthreads();

    if (tid < TOPK) {
        int idx = fi[tid];
        if (idx < 0 || idx >= HW) idx = 0;
        float x = (float)(idx & (WW - 1));
        float y = (float)(idx >> 9);
        float ox = __ldg(off + (size_t)(j * 2 + 0) * HW + idx);
        float oy = __ldg(off + (size_t)(j * 2 + 1) * HW + idx);
        float st = (float)(*stride_p);
        float2 r2;
        r2.x = __fmul_rn(st, __fadd_rn(x, ox));   // bit-exact vs reference
        r2.y = __fmul_rn(st, __fadd_rn(y, oy));
        g_hxy[j][tid] = r2;
    }

    // reset counters for next graph replay (all reads happened before syncs)
    if (tid == 0) { g_count[j] = 0; g_cnth[j] = 0; }
}

// ---------------- kernel 3: nearest-candidate assignment --------------------
// One thread per POSE: j uniform across the warp -> every candidate LDS is a
// broadcast (conflict-free). Pose I/O staged through a shared tile (coalesced).
#define AB 256

__global__ void __launch_bounds__(AB) assign_kernel(const float* __restrict__ poses,
                                                    float* __restrict__ out,
                                                    int N) {
    __shared__ unsigned long long sCX[NJOINT][16];  // packed (-x0,-x1) pairs
    __shared__ unsigned long long sCY[NJOINT][16];
    __shared__ float tile[AB * 34];                 // pose in, result out

    const int tid  = threadIdx.x;
    const int base = blockIdx.x * AB;
    const int npose = min(AB, N - base);

    for (int i = tid; i < NJOINT * (TOPK / 2); i += AB) {
        int jj = i / (TOPK / 2), q = i % (TOPK / 2);
        float2 a = g_hxy[jj][2 * q];
        float2 b = g_hxy[jj][2 * q + 1];
        sCX[jj][q] = pk2(-a.x, -b.x);
        sCY[jj][q] = pk2(-a.y, -b.y);
    }
    {   // coalesced pose tile load (float2)
        const float2* src = (const float2*)(poses + (size_t)base * 34);
        float2* dst = (float2*)tile;
        for (int i = tid; i < npose * NJOINT; i += AB) dst[i] = src[i];
    }
    __syncthreads();

    if (tid < npose) {
        float* mypose = tile + tid * 34;
#pragma unroll 1
        for (int j = 0; j < NJOINT; j++) {
            const float px = mypose[2 * j], py = mypose[2 * j + 1];
            const unsigned long long pxx = pk2(px, px);
            const unsigned long long pyy = pk2(py, py);

            float d2a[TOPK];
#pragma unroll
            for (int q = 0; q < TOPK / 2; q++) {
                unsigned long long dx = add2(pxx, sCX[j][q]);
                unsigned long long dy = add2(pyy, sCY[j][q]);
                unsigned long long d2 = fma2(dy, dy, mul2(dx, dx));
                upk2(d2a[2 * q], d2a[2 * q + 1], d2);
            }

            // 4-chain min for ILP
            float b0 = d2a[0], b1 = d2a[1], b2 = d2a[2], b3 = d2a[3];
#pragma unroll
            for (int k = 4; k < TOPK; k += 4) {
                b0 = fminf(b0, d2a[k]);
                b1 = fminf(b1, d2a[k + 1]);
                b2 = fminf(b2, d2a[k + 2]);
                b3 = fminf(b3, d2a[k + 3]);
            }
            b0 = fminf(b0, d2a[28]); b1 = fminf(b1, d2a[29]);
            const float bd = fminf(fminf(b0, b1), fminf(b2, b3));

            // close-set count + first-occurrence argmin (descending overwrite)
            const float thr = __fmul_rn(bd, 1.0000012f);
            int best = 0, nclose = 0;
#pragma unroll
            for (int k = TOPK - 1; k >= 0; k--) {
                if (d2a[k] <= thr) nclose++;
                if (d2a[k] == bd) best = k;
            }

            float rx, ry;
            if (nclose == 1) {
                float lo, hi;
                upk2(lo, hi, sCX[j][best >> 1]);
                rx = (best & 1) ? -hi : -lo;
                upk2(lo, hi, sCY[j][best >> 1]);
                ry = (best & 1) ? -hi : -lo;
            } else {
                // rare slow path: replicate reference verbatim (rn d2, IEEE
                // sqrt, first-occurrence argmin over sqrt values)
                float bs = FLT_MAX;
                best = 0;
                for (int k = 0; k < TOPK; k++) {
                    float lo, hi, ncx, ncy;
                    upk2(lo, hi, sCX[j][k >> 1]); ncx = (k & 1) ? hi : lo;
                    upk2(lo, hi, sCY[j][k >> 1]); ncy = (k & 1) ? hi : lo;
                    float dx = __fadd_rn(px, ncx);
                    float dy = __fadd_rn(py, ncy);
                    float d  = __fadd_rn(__fmul_rn(dx, dx), __fmul_rn(dy, dy));
                    float sq = sqrtf(d);
                    if (sq < bs) { bs = sq; best = k; }
                }
                float lo, hi;
                upk2(lo, hi, sCX[j][best >> 1]);
                rx = (best & 1) ? -hi : -lo;
                upk2(lo, hi, sCY[j][best >> 1]);
                ry = (best & 1) ? -hi : -lo;
            }
            mypose[2 * j]     = rx;  // pose already consumed for this j
            mypose[2 * j + 1] = ry;
        }
    }
    __syncthreads();

    {   // coalesced result store (float2)
        float2* dst = (float2*)(out + (size_t)base * 34);
        const float2* src = (const float2*)tile;
        for (int i = tid; i < npose * NJOINT; i += AB) dst[i] = src[i];
    }
}

// ---------------- launch ----------------------------------------------------
extern "C" void kernel_launch(void* const* d_in, const int* in_sizes, int n_in,
                              void* d_out, int out_size) {
    const float* poses    = (const float*)d_in[0];   // (N, 34) f32
    const float* heat     = (const float*)d_in[1];   // (17, 512, 512) f32
    const float* off      = (const float*)d_in[2];   // (17, 2, 512, 512) f32
    const int*   stride_p = (const int*)d_in[3];     // scalar

    const int N = in_sizes[0] / 34;

    dim3 g_nms(WW / TW, HH / TH, NJOINT);            // (4, 16, 17)
    nms_kernel<<<g_nms, 1024>>>(heat);

    topk_kernel<<<NJOINT, 1024>>>(off, stride_p);

    assign_kernel<<<(N + AB - 1) / AB, AB>>>(poses, (float*)d_out, N);
}

// round 11
// speedup vs baseline: 1.4429x; 1.0468x over previous
#include <cuda_runtime.h>
#include <float.h>
#include <stdint.h>

#define NJOINT 17
#define HH 512
#define WW 512
#define HW (HH * WW)
#define TOPK 30
#define MAXPEAKS 16384
#define HICAP 1024
#define HTHR 0.999f

// ---------------- scratch (device globals, zero-init at module load) --------
__device__ int    g_count[NJOINT];
__device__ int    g_cnth[NJOINT];
__device__ float  g_pval[NJOINT][MAXPEAKS];
__device__ int    g_pidx[NJOINT][MAXPEAKS];
__device__ float  g_hval[NJOINT][HICAP];
__device__ int    g_hidx[NJOINT][HICAP];
__device__ float2 g_hxy[NJOINT][TOPK];

// ---------------- packed f32x2 helpers --------------------------------------
__device__ __forceinline__ unsigned long long pk2(float lo, float hi) {
    unsigned long long r;
    asm("mov.b64 %0, {%1, %2};" : "=l"(r) : "f"(lo), "f"(hi));
    return r;
}
__device__ __forceinline__ void upk2(float& lo, float& hi, unsigned long long v) {
    asm("mov.b64 {%0, %1}, %2;" : "=f"(lo), "=f"(hi) : "l"(v));
}
__device__ __forceinline__ unsigned long long add2(unsigned long long a, unsigned long long b) {
    unsigned long long r;
    asm("add.rn.f32x2 %0, %1, %2;" : "=l"(r) : "l"(a), "l"(b));
    return r;
}
__device__ __forceinline__ unsigned long long mul2(unsigned long long a, unsigned long long b) {
    unsigned long long r;
    asm("mul.rn.f32x2 %0, %1, %2;" : "=l"(r) : "l"(a), "l"(b));
    return r;
}
__device__ __forceinline__ unsigned long long fma2(unsigned long long a, unsigned long long b,
                                                   unsigned long long c) {
    unsigned long long r;
    asm("fma.rn.f32x2 %0, %1, %2, %3;" : "=l"(r) : "l"(a), "l"(b), "l"(c));
    return r;
}

// ---------------- kernel 1: 5x5 NMS + peak compaction -----------------------
// Tile 128x32 output, halo 2; base aligned down to 4 -> 140 loaded cols.
// Vectorized float4 load + float4 horizontal 5-max.
#define TW 128
#define TH 32
#define LR (TH + 4)      // 36 loaded rows
#define LCV 35           // float4s per row (140 cols)
#define SPITCH 144       // padded row pitch in floats (16B aligned)
#define STAGE 512

__global__ void __launch_bounds__(1024) nms_kernel(const float* __restrict__ heat) {
    __shared__ float s[LR][SPITCH];   // 20.7 KB
    __shared__ float rm[LR][TW];      // 18.4 KB row-max
    __shared__ float stv[STAGE];
    __shared__ int   sti[STAGE];
    __shared__ int   scnt;
    __shared__ int   sbase;

    const int tid  = threadIdx.x;
    const int j    = blockIdx.z;
    const int gx0a = blockIdx.x * TW - 4;   // 4-aligned tile base
    const int gy0  = blockIdx.y * TH - 2;
    const float* hj = heat + (size_t)j * HW;

    if (tid == 0) scnt = 0;

    // ---- load: mostly float4, per-task fallback at borders ----
    for (int i = tid; i < LR * LCV; i += 1024) {
        int ly = i / LCV, lx4 = i - ly * LCV;
        int gy = gy0 + ly;
        int gxs = gx0a + 4 * lx4;
        float4 v;
        bool rowIn = ((unsigned)gy < HH);
        if (rowIn && gxs >= 0 && gxs + 3 < WW) {
            v = __ldg((const float4*)(hj + gy * WW + gxs));
        } else if (rowIn) {
            v.x = ((unsigned)(gxs + 0) < WW) ? __ldg(hj + gy * WW + gxs + 0) : -FLT_MAX;
            v.y = ((unsigned)(gxs + 1) < WW) ? __ldg(hj + gy * WW + gxs + 1) : -FLT_MAX;
            v.z = ((unsigned)(gxs + 2) < WW) ? __ldg(hj + gy * WW + gxs + 2) : -FLT_MAX;
            v.w = ((unsigned)(gxs + 3) < WW) ? __ldg(hj + gy * WW + gxs + 3) : -FLT_MAX;
        } else {
            v = make_float4(-FLT_MAX, -FLT_MAX, -FLT_MAX, -FLT_MAX);
        }
        *(float4*)&s[ly][4 * lx4] = v;
    }
    __syncthreads();

    // ---- horizontal 5-max: 4 outputs/thread via float4 ----
    // output col c (0..127) uses s[ly][c+2 .. c+6]; group c = 4q.
    for (int i = tid; i < LR * 32; i += 1024) {
        int ly = i >> 5, q = i & 31;
        float4 a = *(const float4*)&s[ly][4 * q];       // v0..v3
        float4 b = *(const float4*)&s[ly][4 * q + 4];   // v4..v7
        float4 c = *(const float4*)&s[ly][4 * q + 8];   // v8..v11
        float v2 = a.z, v3 = a.w;
        float v4 = b.x, v5 = b.y, v6 = b.z, v7 = b.w;
        float v8 = c.x, v9 = c.y;
        float m34 = fmaxf(v3, v4), m56 = fmaxf(v5, v6), m78 = fmaxf(v7, v8);
        float4 o;
        o.x = fmaxf(v2, fmaxf(m34, m56));
        o.y = fmaxf(m34, fmaxf(m56, v7));
        o.z = fmaxf(v4, fmaxf(m56, m78));
        o.w = fmaxf(m56, fmaxf(m78, v9));
        *(float4*)&rm[ly][4 * q] = o;
    }
    __syncthreads();

    // ---- vertical 5-max, 4 output rows per thread (shared partials) ----
    {
        const int tx  = tid & 127;
        const int ty0 = (tid >> 7) * 4;
        float a0 = rm[ty0 + 0][tx], a1 = rm[ty0 + 1][tx];
        float a2 = rm[ty0 + 2][tx], a3 = rm[ty0 + 3][tx];
        float a4 = rm[ty0 + 4][tx], a5 = rm[ty0 + 5][tx];
        float a6 = rm[ty0 + 6][tx], a7 = rm[ty0 + 7][tx];
        float t12 = fmaxf(a1, a2), t34 = fmaxf(a3, a4), t56 = fmaxf(a5, a6);
        float mm[4];
        mm[0] = fmaxf(a0, fmaxf(t12, t34));
        mm[1] = fmaxf(t12, fmaxf(t34, a5));
        mm[2] = fmaxf(a2, fmaxf(t34, t56));
        mm[3] = fmaxf(t34, fmaxf(t56, a7));
        float cc[4];
        cc[0] = s[ty0 + 2][tx + 4];   // center: tile base shifted by -4
        cc[1] = s[ty0 + 3][tx + 4];
        cc[2] = s[ty0 + 4][tx + 4];
        cc[3] = s[ty0 + 5][tx + 4];
        const int gx = blockIdx.x * TW + tx;
        const int gyb = blockIdx.y * TH + ty0;
#pragma unroll
        for (int r = 0; r < 4; r++) {
            if (cc[r] == mm[r]) {
                int idx = (gyb + r) * WW + gx;
                int p = atomicAdd(&scnt, 1);
                if (p < STAGE) { stv[p] = cc[r]; sti[p] = idx; }
                if (cc[r] > HTHR) {
                    int hp = atomicAdd(&g_cnth[j], 1);
                    if (hp < HICAP) { g_hval[j][hp] = cc[r]; g_hidx[j][hp] = idx; }
                }
            }
        }
    }
    __syncthreads();

    if (tid == 0) sbase = atomicAdd(&g_count[j], min(scnt, STAGE));
    __syncthreads();

    const int cnt = min(scnt, STAGE), base = sbase;
    for (int i = tid; i < cnt; i += 1024) {
        int d = base + i;
        if (d < MAXPEAKS) {
            g_pval[j][d] = stv[i];
            g_pidx[j][d] = sti[i];
        }
    }
}

// ---------------- kernel 2: top-30 per joint + heat_xy ----------------------
__device__ __forceinline__ bool better(float v1, int i1, float v2, int i2) {
    // descending value, ascending index tie-break (jax.lax.top_k stable order)
    return (v1 > v2) || (v1 == v2 && i1 < i2);
}

template <int NR>
__device__ __forceinline__ void warp_top30(float* v, int* id, float* outv, int* outi) {
    for (int r = 0; r < TOPK; r++) {
        float bv = -FLT_MAX;
        int   bi = 0x7fffffff;
#pragma unroll
        for (int s = 0; s < NR; s++)
            if (better(v[s], id[s], bv, bi)) { bv = v[s]; bi = id[s]; }
#pragma unroll
        for (int o = 16; o > 0; o >>= 1) {
            float ov = __shfl_down_sync(0xffffffffu, bv, o);
            int   oi = __shfl_down_sync(0xffffffffu, bi, o);
            if (better(ov, oi, bv, bi)) { bv = ov; bi = oi; }
        }
        bv = __shfl_sync(0xffffffffu, bv, 0);
        bi = __shfl_sync(0xffffffffu, bi, 0);
        if ((threadIdx.x & 31) == 0) { outv[r] = bv; outi[r] = bi; }
#pragma unroll
        for (int s = 0; s < NR; s++)
            if (id[s] == bi) v[s] = -FLT_MAX;  // winner ids unique
    }
}

__global__ void __launch_bounds__(1024) topk_kernel(const float* __restrict__ off,
                                                    const int* __restrict__ stride_p) {
    __shared__ float wv1[32][TOPK];
    __shared__ int   wi1[32][TOPK];
    __shared__ float wv2[8][TOPK];
    __shared__ int   wi2[8][TOPK];
    __shared__ float fv[TOPK];
    __shared__ int   fi[TOPK];

    const int tid  = threadIdx.x;
    const int w    = tid >> 5;
    const int lane = tid & 31;
    const int j    = blockIdx.x;

    const int n_high = g_cnth[j];
    const bool useHigh = (n_high >= TOPK) && (n_high <= HICAP);

    if (useHigh) {
        // fast path: all top-30 values exceed HTHR and live in the high list
        float v[1];
        int   id[1];
        if (tid < n_high) { v[0] = g_hval[j][tid]; id[0] = g_hidx[j][tid]; }
        else              { v[0] = -FLT_MAX;       id[0] = 0x7fffffff;     }
        warp_top30<1>(v, id, wv1[w], wi1[w]);
    } else {
        int n = g_count[j];
        if (n > MAXPEAKS) n = MAXPEAKS;
        float v[16];
        int   id[16];
#pragma unroll
        for (int s = 0; s < 16; s++) {
            int i = tid + s * 1024;
            if (i < n) { v[s] = g_pval[j][i]; id[s] = g_pidx[j][i]; }
            else       { v[s] = -FLT_MAX;     id[s] = 0x7fffffff;   }
        }
        warp_top30<16>(v, id, wv1[w], wi1[w]);
    }
    __syncthreads();

    if (w < 8) {  // merge 4 warp lists each
        float v2[4];
        int   id2[4];
#pragma unroll
        for (int s = 0; s < 4; s++) {
            int e = lane + 32 * s;
            if (e < 4 * TOPK) {
                int L = w * 4 + e / TOPK, r = e % TOPK;
                v2[s] = wv1[L][r]; id2[s] = wi1[L][r];
            } else { v2[s] = -FLT_MAX; id2[s] = 0x7fffffff; }
        }
        warp_top30<4>(v2, id2, wv2[w], wi2[w]);
    }
    __syncthreads();

    if (w == 0) {  // final merge of 8 lists
        float v3[8];
        int   id3[8];
#pragma unroll
        for (int s = 0; s < 8; s++) {
            int e = lane + 32 * s;
            if (e < 8 * TOPK) {
                int L = e / TOPK, r = e % TOPK;
                v3[s] = wv2[L][r]; id3[s] = wi2[L][r];
            } else { v3[s] = -FLT_MAX; id3[s] = 0x7fffffff; }
        }
        warp_top30<8>(v3, id3, fv, fi);
    }
    __syncthreads();

    if (tid < TOPK) {
        int idx = fi[tid];
        if (idx < 0 || idx >= HW) idx = 0;
        float x = (float)(idx & (WW - 1));
        float y = (float)(idx >> 9);
        float ox = __ldg(off + (size_t)(j * 2 + 0) * HW + idx);
        float oy = __ldg(off + (size_t)(j * 2 + 1) * HW + idx);
        float st = (float)(*stride_p);
        float2 r2;
        r2.x = __fmul_rn(st, __fadd_rn(x, ox));   // bit-exact vs reference
        r2.y = __fmul_rn(st, __fadd_rn(y, oy));
        g_hxy[j][tid] = r2;
    }

    // reset counters for next graph replay (all reads happened before syncs)
    if (tid == 0) { g_count[j] = 0; g_cnth[j] = 0; }
}

// ---------------- kernel 3: nearest-candidate assignment --------------------
// One thread per POSE: j uniform across the warp -> every candidate LDS is a
// broadcast (conflict-free). Pose I/O staged through a shared tile (coalesced).
#define AB 256

__global__ void __launch_bounds__(AB) assign_kernel(const float* __restrict__ poses,
                                                    float* __restrict__ out,
                                                    int N) {
    __shared__ unsigned long long sCX[NJOINT][16];  // packed (-x0,-x1) pairs
    __shared__ unsigned long long sCY[NJOINT][16];
    __shared__ float tile[AB * 34];                 // pose in, result out

    const int tid  = threadIdx.x;
    const int base = blockIdx.x * AB;
    const int npose = min(AB, N - base);

    for (int i = tid; i < NJOINT * (TOPK / 2); i += AB) {
        int jj = i / (TOPK / 2), q = i % (TOPK / 2);
        float2 a = g_hxy[jj][2 * q];
        float2 b = g_hxy[jj][2 * q + 1];
        sCX[jj][q] = pk2(-a.x, -b.x);
        sCY[jj][q] = pk2(-a.y, -b.y);
    }
    {   // coalesced pose tile load (float2)
        const float2* src = (const float2*)(poses + (size_t)base * 34);
        float2* dst = (float2*)tile;
        for (int i = tid; i < npose * NJOINT; i += AB) dst[i] = src[i];
    }
    __syncthreads();

    if (tid < npose) {
        float* mypose = tile + tid * 34;
#pragma unroll 1
        for (int j = 0; j < NJOINT; j++) {
            const float px = mypose[2 * j], py = mypose[2 * j + 1];
            const unsigned long long pxx = pk2(px, px);
            const unsigned long long pyy = pk2(py, py);

            float d2a[TOPK];
#pragma unroll
            for (int q = 0; q < TOPK / 2; q++) {
                unsigned long long dx = add2(pxx, sCX[j][q]);
                unsigned long long dy = add2(pyy, sCY[j][q]);
                unsigned long long d2 = fma2(dy, dy, mul2(dx, dx));
                upk2(d2a[2 * q], d2a[2 * q + 1], d2);
            }

            // 4-chain min for ILP
            float b0 = d2a[0], b1 = d2a[1], b2 = d2a[2], b3 = d2a[3];
#pragma unroll
            for (int k = 4; k < TOPK; k += 4) {
                b0 = fminf(b0, d2a[k]);
                b1 = fminf(b1, d2a[k + 1]);
                b2 = fminf(b2, d2a[k + 2]);
                b3 = fminf(b3, d2a[k + 3]);
            }
            b0 = fminf(b0, d2a[28]); b1 = fminf(b1, d2a[29]);
            const float bd = fminf(fminf(b0, b1), fminf(b2, b3));

            // close-set count + first-occurrence argmin (descending overwrite)
            const float thr = __fmul_rn(bd, 1.0000012f);
            int best = 0, nclose = 0;
#pragma unroll
            for (int k = TOPK - 1; k >= 0; k--) {
                if (d2a[k] <= thr) nclose++;
                if (d2a[k] == bd) best = k;
            }

            float rx, ry;
            if (nclose == 1) {
                float lo, hi;
                upk2(lo, hi, sCX[j][best >> 1]);
                rx = (best & 1) ? -hi : -lo;
                upk2(lo, hi, sCY[j][best >> 1]);
                ry = (best & 1) ? -hi : -lo;
            } else {
                // rare slow path: replicate reference verbatim (rn d2, IEEE
                // sqrt, first-occurrence argmin over sqrt values)
                float bs = FLT_MAX;
                best = 0;
                for (int k = 0; k < TOPK; k++) {
                    float lo, hi, ncx, ncy;
                    upk2(lo, hi, sCX[j][k >> 1]); ncx = (k & 1) ? hi : lo;
                    upk2(lo, hi, sCY[j][k >> 1]); ncy = (k & 1) ? hi : lo;
                    float dx = __fadd_rn(px, ncx);
                    float dy = __fadd_rn(py, ncy);
                    float d  = __fadd_rn(__fmul_rn(dx, dx), __fmul_rn(dy, dy));
                    float sq = sqrtf(d);
                    if (sq < bs) { bs = sq; best = k; }
                }
                float lo, hi;
                upk2(lo, hi, sCX[j][best >> 1]);
                rx = (best & 1) ? -hi : -lo;
                upk2(lo, hi, sCY[j][best >> 1]);
                ry = (best & 1) ? -hi : -lo;
            }
            mypose[2 * j]     = rx;  // pose already consumed for this j
            mypose[2 * j + 1] = ry;
        }
    }
    __syncthreads();

    {   // coalesced result store (float2)
        float2* dst = (float2*)(out + (size_t)base * 34);
        const float2* src = (const float2*)tile;
        for (int i = tid; i < npose * NJOINT; i += AB) dst[i] = src[i];
    }
}

// ---------------- launch ----------------------------------------------------
extern "C" void kernel_launch(void* const* d_in, const int* in_sizes, int n_in,
                              void* d_out, int out_size) {
    const float* poses    = (const float*)d_in[0];   // (N, 34) f32
    const float* heat     = (const float*)d_in[1];   // (17, 512, 512) f32
    const float* off      = (const float*)d_in[2];   // (17, 2, 512, 512) f32
    const int*   stride_p = (const int*)d_in[3];     // scalar

    const int N = in_sizes[0] / 34;

    dim3 g_nms(WW / TW, HH / TH, NJOINT);            // (4, 16, 17)
    nms_kernel<<<g_nms, 1024>>>(heat);

    topk_kernel<<<NJOINT, 1024>>>(off, stride_p);

    assign_kernel<<<(N + AB - 1) / AB, AB>>>(poses, (float*)d_out, N);
}